// round 16
// baseline (speedup 1.0000x reference)
#include <cuda_runtime.h>
#include <cuda_bf16.h>
#include <math.h>

// ---------------------------------------------------------------------------
// Problem constants (fixed-shape instance)
// ---------------------------------------------------------------------------
#define B_    2
#define Q_    900
#define C_    256
#define NCAM  6
#define BQ    (B_ * Q_)          // 1800
#define BNQ   (B_ * NCAM * Q_)   // 10800

// ---------------------------------------------------------------------------
// Scratch (device globals; no dynamic allocation allowed)
// ---------------------------------------------------------------------------
__device__ float g_maskf[BQ];
__device__ float g_keep[BQ];
__device__ float g_invext[B_ * NCAM * 16];
__device__ __align__(16) __nv_bfloat16 g_ms_hi[BNQ * C_];   // 5.5 MB
__device__ __align__(16) __nv_bfloat16 g_ms_lo[BNQ * C_];
__device__ __align__(16) float g_q[BQ * C_];
__device__ __align__(16) float g_v[BNQ * C_];               // 11 MB
__device__ __align__(16) __nv_bfloat16 g_fu_hi[BQ * C_];
__device__ __align__(16) __nv_bfloat16 g_fu_lo[BQ * C_];
__device__ __align__(16) __nv_bfloat16 g_wv_hi[C_ * C_], g_wv_lo[C_ * C_];
__device__ __align__(16) __nv_bfloat16 g_wo_hi[C_ * C_], g_wo_lo[C_ * C_];

// ---------------------------------------------------------------------------
// MMA helpers (sm_80+ HMMA bf16, fp32 accumulate)
// ---------------------------------------------------------------------------
__device__ __forceinline__ void ldsm4(unsigned* r, unsigned addr) {
    asm volatile("ldmatrix.sync.aligned.m8n8.x4.shared.b16 {%0,%1,%2,%3}, [%4];"
        : "=r"(r[0]), "=r"(r[1]), "=r"(r[2]), "=r"(r[3]) : "r"(addr));
}
__device__ __forceinline__ void mma16816(float* c, const unsigned* a, const unsigned* b) {
    asm volatile(
        "mma.sync.aligned.m16n8k16.row.col.f32.bf16.bf16.f32 "
        "{%0,%1,%2,%3}, {%4,%5,%6,%7}, {%8,%9}, {%0,%1,%2,%3};"
        : "+f"(c[0]), "+f"(c[1]), "+f"(c[2]), "+f"(c[3])
        : "r"(a[0]), "r"(a[1]), "r"(a[2]), "r"(a[3]), "r"(b[0]), "r"(b[1]));
}
__device__ __forceinline__ void split_bf16(float v, __nv_bfloat16& hi, __nv_bfloat16& lo) {
    hi = __float2bfloat16(v);
    lo = __float2bfloat16(v - __bfloat162float(hi));
}

// ---------------------------------------------------------------------------
// Kernel 1: mask dtype detection + mask arrays + 4x4 extrinsic inverses.
// Inverse via 2x2-complementary-minor (s/c) formulation, one thread per
// matrix, ALL static register indexing (no local-memory spill, no LDL).
// ---------------------------------------------------------------------------
__global__ void prep_kernel(const void* __restrict__ mask_raw,
                            const float* __restrict__ ext)
{
    __shared__ int s_byte;
    if (threadIdx.x == 0) s_byte = 0;
    __syncthreads();

    const unsigned int* w = (const unsigned int*)mask_raw;
    for (int i = threadIdx.x; i < 450; i += blockDim.x) {
        unsigned int x = w[i];
        if (x != 0u && x != 1u && x != 0x3F800000u) atomicOr(&s_byte, 1);
    }
    __syncthreads();
    const bool isbyte = (s_byte != 0);
    const unsigned char* bytes = (const unsigned char*)mask_raw;
    for (int i = threadIdx.x; i < BQ; i += blockDim.x) {
        bool mk = isbyte ? (bytes[i] != 0) : (w[i] != 0u);
        g_maskf[i] = mk ? 1.0f : 0.0f;
        g_keep[i]  = mk ? 0.0f : 1.0f;
    }

    const int t = threadIdx.x;
    if (t < B_ * NCAM) {
        const float* e = ext + t * 16;
        const double m00 = e[0],  m01 = e[1],  m02 = e[2],  m03 = e[3];
        const double m10 = e[4],  m11 = e[5],  m12 = e[6],  m13 = e[7];
        const double m20 = e[8],  m21 = e[9],  m22 = e[10], m23 = e[11];
        const double m30 = e[12], m31 = e[13], m32 = e[14], m33 = e[15];

        const double s0 = m00*m11 - m10*m01;
        const double s1 = m00*m12 - m10*m02;
        const double s2 = m00*m13 - m10*m03;
        const double s3 = m01*m12 - m11*m02;
        const double s4 = m01*m13 - m11*m03;
        const double s5 = m02*m13 - m12*m03;

        const double c5 = m22*m33 - m32*m23;
        const double c4 = m21*m33 - m31*m23;
        const double c3 = m21*m32 - m31*m22;
        const double c2 = m20*m33 - m30*m23;
        const double c1 = m20*m32 - m30*m22;
        const double c0 = m20*m31 - m30*m21;

        const double det = s0*c5 - s1*c4 + s2*c3 + s3*c2 - s4*c1 + s5*c0;
        const double rd  = 1.0 / det;

        double inv[16];
        inv[0]  = ( m11*c5 - m12*c4 + m13*c3) * rd;
        inv[1]  = (-m01*c5 + m02*c4 - m03*c3) * rd;
        inv[2]  = ( m31*s5 - m32*s4 + m33*s3) * rd;
        inv[3]  = (-m21*s5 + m22*s4 - m23*s3) * rd;
        inv[4]  = (-m10*c5 + m12*c2 - m13*c1) * rd;
        inv[5]  = ( m00*c5 - m02*c2 + m03*c1) * rd;
        inv[6]  = (-m30*s5 + m32*s2 - m33*s1) * rd;
        inv[7]  = ( m20*s5 - m22*s2 + m23*s1) * rd;
        inv[8]  = ( m10*c4 - m11*c2 + m13*c0) * rd;
        inv[9]  = (-m00*c4 + m01*c2 - m03*c0) * rd;
        inv[10] = ( m30*s4 - m31*s2 + m33*s0) * rd;
        inv[11] = (-m20*s4 + m21*s2 - m23*s0) * rd;
        inv[12] = (-m10*c3 + m11*c1 - m12*c0) * rd;
        inv[13] = ( m00*c3 - m01*c1 + m02*c0) * rd;
        inv[14] = (-m30*s3 + m31*s1 - m32*s0) * rd;
        inv[15] = ( m20*s3 - m21*s1 + m22*s0) * rd;

#pragma unroll
        for (int i = 0; i < 16; i++) {
            float v = (float)inv[i];
            if (isnan(v)) v = 0.0f;
            else if (isinf(v)) v = (v > 0.0f) ? 1e6f : -1e6f;
            g_invext[t * 16 + i] = v;
        }
    }
}

// ---------------------------------------------------------------------------
// Kernel: weight fp32 -> bf16 hi/lo split (65536 elements)
// ---------------------------------------------------------------------------
__global__ void wconv_kernel(const float* __restrict__ src,
                             __nv_bfloat16* __restrict__ hi,
                             __nv_bfloat16* __restrict__ lo)
{
    int i = blockIdx.x * 256 + threadIdx.x;
    float v = src[i];
    __nv_bfloat16 h, l;
    split_bf16(v, h, l);
    hi[i] = h; lo[i] = l;
}

// ---------------------------------------------------------------------------
// Kernel 2: projection + bilinear sampling (fused), emits bf16 hi/lo
// ---------------------------------------------------------------------------
__global__ void sample_kernel(const float* __restrict__ refp,
                              const float* __restrict__ intr,
                              const float* __restrict__ f0,
                              const float* __restrict__ f1,
                              const float* __restrict__ f2,
                              const float* __restrict__ f3)
{
    const int p  = blockIdx.x;       // (b*N+n)*Q + q
    const int bn = p / Q_;
    const int qq = p % Q_;
    const int b  = bn / NCAM;

    __shared__ int   sidx[16];
    __shared__ float sw[16];

    const int tid = threadIdx.x;
    if (tid < 4) {
        float rx, ry, rz;
        if (g_maskf[b * Q_ + qq] != 0.0f) {
            rx = ry = rz = -1000.0f;
        } else {
            const float* rp = refp + (b * Q_ + qq) * 3;
            rx = rp[0] * 102.4f - 51.2f;
            ry = rp[1] * 102.4f - 51.2f;
            rz = rp[2] * 102.4f - 51.2f;
        }
        const float* M = g_invext + bn * 16;
        float pch[4];
#pragma unroll
        for (int i = 0; i < 4; i++)
            pch[i] = M[i*4+0]*rx + M[i*4+1]*ry + M[i*4+2]*rz + M[i*4+3];

        float d = pch[2];
        if (isnan(d)) d = 10.0f;
        else if (isinf(d)) d = (d > 0.0f) ? 100.0f : -100.0f;
        const int invd = d < 1.5f;
        const float ds = fmaxf(d, 1.5f);
        const float pc0 = pch[0] / ds, pc1 = pch[1] / ds, pc2 = pch[2] / ds;

        const float* K = intr + bn * 9;
        float ix = K[0]*pc0 + K[1]*pc1 + K[2]*pc2;
        float iy = K[3]*pc0 + K[4]*pc1 + K[5]*pc2;
        ix = fminf(fmaxf(ix, -3000.0f), 3000.0f);
        iy = fminf(fmaxf(iy, -3000.0f), 3000.0f);

        const int l = tid;
        const int WFs[4] = {200, 100, 50, 25};
        const int HFs[4] = {112, 56, 28, 14};
        const float scl[4] = {0.25f, 0.125f, 0.0625f, 0.03125f};
        const int Wf = WFs[l], Hf = HFs[l];
        float gx, gy;
        if (invd) {
            gx = -100.0f; gy = -100.0f;
        } else {
            float fx = ix * scl[l];
            float fy = iy * scl[l];
            gx = fx / (float)(Wf - 1) * 2.0f - 1.0f;
            gy = fy / (float)(Hf - 1) * 2.0f - 1.0f;
            gx = fminf(fmaxf(gx, -10.0f), 10.0f);
            gy = fminf(fmaxf(gy, -10.0f), 10.0f);
        }
        float px = (gx + 1.0f) * 0.5f * (float)(Wf - 1);
        float py = (gy + 1.0f) * 0.5f * (float)(Hf - 1);
        float x0f = floorf(px), y0f = floorf(py);
        int x0 = (int)x0f, y0 = (int)y0f;
        float wx1 = px - x0f, wy1 = py - y0f;
        float wx0 = 1.0f - wx1, wy0 = 1.0f - wy1;

        int   cx[4] = {x0, x0 + 1, x0, x0 + 1};
        int   cy[4] = {y0, y0, y0 + 1, y0 + 1};
        float cw[4] = {wx0 * wy0, wx1 * wy0, wx0 * wy1, wx1 * wy1};
#pragma unroll
        for (int k = 0; k < 4; k++) {
            int xi = cx[k], yi = cy[k];
            bool valid = (xi >= 0) && (xi < Wf) && (yi >= 0) && (yi < Hf);
            int xc = min(max(xi, 0), Wf - 1);
            int yc = min(max(yi, 0), Hf - 1);
            sidx[l * 4 + k] = yc * Wf + xc;
            sw[l * 4 + k]   = valid ? cw[k] : 0.0f;
        }
    }
    __syncthreads();

    const int c = tid;
    const float* base0 = f0 + (size_t)(bn * C_ + c) * 22400;
    const float* base1 = f1 + (size_t)(bn * C_ + c) * 5600;
    const float* base2 = f2 + (size_t)(bn * C_ + c) * 1400;
    const float* base3 = f3 + (size_t)(bn * C_ + c) * 350;
    const float* bases[4] = {base0, base1, base2, base3};

    float sum = 0.0f;
#pragma unroll
    for (int l = 0; l < 4; l++) {
#pragma unroll
        for (int k = 0; k < 4; k++) {
            float w = sw[l * 4 + k];
            if (w != 0.0f) sum += w * __ldg(&bases[l][sidx[l * 4 + k]]);
        }
    }
    float v = 0.25f * sum;
    __nv_bfloat16 hi, lo;
    split_bf16(v, hi, lo);
    const size_t off = (size_t)p * C_ + c;
    g_ms_hi[off] = hi;
    g_ms_lo[off] = lo;
}

// ---------------------------------------------------------------------------
// Tensor-core GEMM (bf16x3 decomposition, fp32 accumulate):
// out[m, j] = (sum_k A[m,k] * W[j,k] + bias[j]) * keep[m]
// Block 128(M) x 64(N), 8 warps, warp tile 32x32. grid (4, ceil(M/128)).
// ---------------------------------------------------------------------------
#define KSTR 24   // smem row stride in bf16 (48B: 16B-aligned, ldmatrix conflict-free)

__global__ __launch_bounds__(256) void mma_gemm(
    const __nv_bfloat16* __restrict__ Ahi, const __nv_bfloat16* __restrict__ Alo,
    const __nv_bfloat16* __restrict__ Bhi, const __nv_bfloat16* __restrict__ Blo,
    const float* __restrict__ bias, const float* __restrict__ keep,
    float* __restrict__ out, int M)
{
    __shared__ __align__(16) __nv_bfloat16 sA[2][2][128 * KSTR];
    __shared__ __align__(16) __nv_bfloat16 sB[2][2][64 * KSTR];

    const int tid  = threadIdx.x;
    const int lane = tid & 31, warp = tid >> 5;
    const int wm = warp & 3, wn = warp >> 2;
    const int row0 = blockIdx.y * 128, col0 = blockIdx.x * 64;

    const int ar = tid >> 1;                 // 0..127
    const int ak = (tid & 1) * 8;            // 0 / 8
    const int garow = min(row0 + ar, M - 1);
    const __nv_bfloat16* pAhi = Ahi + (size_t)garow * 256 + ak;
    const __nv_bfloat16* pAlo = Alo + (size_t)garow * 256 + ak;
    const int bsel = tid >> 7;               // 0: hi, 1: lo
    const int br = (tid & 127) >> 1;         // 0..63
    const int bk = (tid & 1) * 8;
    const __nv_bfloat16* pB = (bsel ? Blo : Bhi) + (size_t)(col0 + br) * 256 + bk;

    const int sa_off = ar * KSTR + ak;
    const int sb_off = br * KSTR + bk;

    float acc[2][4][4];
#pragma unroll
    for (int i = 0; i < 2; i++)
#pragma unroll
        for (int j = 0; j < 4; j++)
#pragma unroll
            for (int k = 0; k < 4; k++) acc[i][j][k] = 0.0f;

    uint4 ah = *(const uint4*)pAhi;
    uint4 al = *(const uint4*)pAlo;
    uint4 bb = *(const uint4*)pB;
    *(uint4*)&sA[0][0][sa_off] = ah;
    *(uint4*)&sA[0][1][sa_off] = al;
    *(uint4*)&sB[0][bsel][sb_off] = bb;
    __syncthreads();

    const int a_r = lane & 15;
    const int a_c = (lane >> 4) * 8;
    const int b_n = (lane & 7) + ((lane & 16) ? 8 : 0);
    const int b_k = (lane & 8) ? 8 : 0;

#pragma unroll 1
    for (int t = 0; t < 16; t++) {
        const int buf = t & 1;
        if (t < 15) {
            const int k0 = (t + 1) * 16;
            ah = *(const uint4*)(pAhi + k0);
            al = *(const uint4*)(pAlo + k0);
            bb = *(const uint4*)(pB + k0);
        }

        unsigned afh[2][4], afl[2][4], bfh[2][4], bfl[2][4];
#pragma unroll
        for (int mf = 0; mf < 2; mf++) {
            const int rbase = (wm * 32 + mf * 16 + a_r) * KSTR + a_c;
            ldsm4(afh[mf], (unsigned)__cvta_generic_to_shared(&sA[buf][0][rbase]));
            ldsm4(afl[mf], (unsigned)__cvta_generic_to_shared(&sA[buf][1][rbase]));
        }
#pragma unroll
        for (int nf2 = 0; nf2 < 2; nf2++) {
            const int nbase = (wn * 32 + nf2 * 16 + b_n) * KSTR + b_k;
            ldsm4(bfh[nf2], (unsigned)__cvta_generic_to_shared(&sB[buf][0][nbase]));
            ldsm4(bfl[nf2], (unsigned)__cvta_generic_to_shared(&sB[buf][1][nbase]));
        }
#pragma unroll
        for (int mf = 0; mf < 2; mf++)
#pragma unroll
            for (int nf = 0; nf < 4; nf++) {
                const int nf2 = nf >> 1, h = (nf & 1) * 2;
                mma16816(acc[mf][nf], afh[mf], &bfh[nf2][h]);   // hi*hi
                mma16816(acc[mf][nf], afh[mf], &bfl[nf2][h]);   // hi*lo
                mma16816(acc[mf][nf], afl[mf], &bfh[nf2][h]);   // lo*hi
            }

        if (t < 15) {
            const int nb = buf ^ 1;
            *(uint4*)&sA[nb][0][sa_off] = ah;
            *(uint4*)&sA[nb][1][sa_off] = al;
            *(uint4*)&sB[nb][bsel][sb_off] = bb;
        }
        __syncthreads();
    }

#pragma unroll
    for (int mf = 0; mf < 2; mf++)
#pragma unroll
        for (int nf = 0; nf < 4; nf++) {
            const int r  = row0 + wm * 32 + mf * 16 + (lane >> 2);
            const int cg = col0 + wn * 32 + nf * 8 + (lane & 3) * 2;
            const float b0v = bias[cg], b1v = bias[cg + 1];
            if (r < M) {
                const float ks = keep ? keep[r] : 1.0f;
                float2 o = make_float2((acc[mf][nf][0] + b0v) * ks,
                                       (acc[mf][nf][1] + b1v) * ks);
                *(float2*)(out + (size_t)r * 256 + cg) = o;
            }
            const int r2 = r + 8;
            if (r2 < M) {
                const float ks = keep ? keep[r2] : 1.0f;
                float2 o = make_float2((acc[mf][nf][2] + b0v) * ks,
                                       (acc[mf][nf][3] + b1v) * ks);
                *(float2*)(out + (size_t)r2 * 256 + cg) = o;
            }
        }
}

// ---------------------------------------------------------------------------
// SGEMM 64x64 (fp32 SIMT) — kept for the fully-overlapped q projection
// ---------------------------------------------------------------------------
__global__ __launch_bounds__(256) void sgemm64(const float* __restrict__ A,
                                               const float* __restrict__ W,
                                               const float* __restrict__ bias,
                                               const float* __restrict__ keep,
                                               float* __restrict__ out, int M)
{
    __shared__ float As[2][16][68];
    __shared__ float Bs[2][16][68];

    const int tid  = threadIdx.x;
    const int row0 = blockIdx.y * 64;
    const int col0 = blockIdx.x * 64;

    const int tx = tid & 15;
    const int ty = tid >> 4;
    const int lr = tid >> 2;
    const int lk = (tid & 3) * 4;

    const int gr = row0 + lr;
    const float* Aptr = A + (size_t)gr * 256 + lk;
    const float* Wptr = W + (size_t)(col0 + lr) * 256 + lk;

    float acc[4][4];
#pragma unroll
    for (int i = 0; i < 4; i++)
#pragma unroll
        for (int j = 0; j < 4; j++) acc[i][j] = 0.0f;

    float4 av = (gr < M) ? *(const float4*)(Aptr) : make_float4(0.f,0.f,0.f,0.f);
    float4 bv = *(const float4*)(Wptr);
    As[0][lk+0][lr]=av.x; As[0][lk+1][lr]=av.y; As[0][lk+2][lr]=av.z; As[0][lk+3][lr]=av.w;
    Bs[0][lk+0][lr]=bv.x; Bs[0][lk+1][lr]=bv.y; Bs[0][lk+2][lr]=bv.z; Bs[0][lk+3][lr]=bv.w;
    __syncthreads();

#pragma unroll 1
    for (int t = 0; t < 16; t++) {
        const int buf = t & 1;
        if (t < 15) {
            const int k0 = (t + 1) * 16;
            av = (gr < M) ? *(const float4*)(Aptr + k0) : make_float4(0.f,0.f,0.f,0.f);
            bv = *(const float4*)(Wptr + k0);
        }
#pragma unroll
        for (int kk = 0; kk < 16; kk++) {
            float a[4], b[4];
            *(float4*)a = *(const float4*)&As[buf][kk][ty * 4];
            *(float4*)b = *(const float4*)&Bs[buf][kk][tx * 4];
#pragma unroll
            for (int i = 0; i < 4; i++)
#pragma unroll
                for (int j = 0; j < 4; j++) acc[i][j] += a[i] * b[j];
        }
        if (t < 15) {
            const int nb = buf ^ 1;
            As[nb][lk+0][lr]=av.x; As[nb][lk+1][lr]=av.y; As[nb][lk+2][lr]=av.z; As[nb][lk+3][lr]=av.w;
            Bs[nb][lk+0][lr]=bv.x; Bs[nb][lk+1][lr]=bv.y; Bs[nb][lk+2][lr]=bv.z; Bs[nb][lk+3][lr]=bv.w;
        }
        __syncthreads();
    }

    const float4 bias4 = *(const float4*)(bias + col0 + tx * 4);
#pragma unroll
    for (int i = 0; i < 4; i++) {
        int r = row0 + ty * 4 + i;
        if (r >= M) continue;
        float ks = keep ? keep[r] : 1.0f;
        float4 o;
        o.x = (acc[i][0] + bias4.x) * ks;
        o.y = (acc[i][1] + bias4.y) * ks;
        o.z = (acc[i][2] + bias4.z) * ks;
        o.w = (acc[i][3] + bias4.w) * ks;
        *(float4*)(out + (size_t)r * 256 + col0 + tx * 4) = o;
    }
}

// ---------------------------------------------------------------------------
// Kernel: max over cameras + fused = relu(q + max) + q; emits bf16 hi/lo
// ---------------------------------------------------------------------------
__global__ void maxfuse_kernel()
{
    int idx = blockIdx.x * blockDim.x + threadIdx.x;   // over BQ * C/4
    if (idx >= BQ * (C_ / 4)) return;
    int m = idx / (C_ / 4);        // b*Q + q
    int c4 = idx % (C_ / 4);
    int b = m / Q_, qq = m % Q_;

    float4 mx = make_float4(-INFINITY, -INFINITY, -INFINITY, -INFINITY);
#pragma unroll
    for (int n = 0; n < NCAM; n++) {
        const float4 v = *(const float4*)&g_v[(((size_t)(b * NCAM + n) * Q_ + qq) * C_) + c4 * 4];
        mx.x = fmaxf(mx.x, v.x); mx.y = fmaxf(mx.y, v.y);
        mx.z = fmaxf(mx.z, v.z); mx.w = fmaxf(mx.w, v.w);
    }
    const float4 qv = *(const float4*)&g_q[(size_t)m * C_ + c4 * 4];
    float f[4];
    f[0] = fmaxf(qv.x + mx.x, 0.0f) + qv.x;
    f[1] = fmaxf(qv.y + mx.y, 0.0f) + qv.y;
    f[2] = fmaxf(qv.z + mx.z, 0.0f) + qv.z;
    f[3] = fmaxf(qv.w + mx.w, 0.0f) + qv.w;
    const size_t off = (size_t)m * C_ + c4 * 4;
#pragma unroll
    for (int i = 0; i < 4; i++) {
        __nv_bfloat16 hi, lo;
        split_bf16(f[i], hi, lo);
        g_fu_hi[off + i] = hi;
        g_fu_lo[off + i] = lo;
    }
}

// ---------------------------------------------------------------------------
// Launch. Side stream: weight splits + q-projection GEMM, overlapped with
// prep/sample/v-GEMM on the main stream.
// ---------------------------------------------------------------------------
extern "C" void kernel_launch(void* const* d_in, const int* in_sizes, int n_in,
                              void* d_out, int out_size)
{
    const float* query = (const float*)d_in[0];
    const float* refp  = (const float*)d_in[1];
    const void*  mask  = d_in[2];
    const float* intr  = (const float*)d_in[3];
    const float* ext   = (const float*)d_in[4];
    const float* f0    = (const float*)d_in[5];
    const float* f1    = (const float*)d_in[6];
    const float* f2    = (const float*)d_in[7];
    const float* f3    = (const float*)d_in[8];
    const float* Wq    = (const float*)d_in[9];
    const float* bq    = (const float*)d_in[10];
    const float* Wv    = (const float*)d_in[11];
    const float* bv    = (const float*)d_in[12];
    const float* Wo    = (const float*)d_in[13];
    const float* bo    = (const float*)d_in[14];
    float* out = (float*)d_out;

    float *p_q, *p_v, *p_keep;
    __nv_bfloat16 *p_ms_hi, *p_ms_lo, *p_fu_hi, *p_fu_lo;
    __nv_bfloat16 *p_wv_hi, *p_wv_lo, *p_wo_hi, *p_wo_lo;
    cudaGetSymbolAddress((void**)&p_q,     g_q);
    cudaGetSymbolAddress((void**)&p_v,     g_v);
    cudaGetSymbolAddress((void**)&p_keep,  g_keep);
    cudaGetSymbolAddress((void**)&p_ms_hi, g_ms_hi);
    cudaGetSymbolAddress((void**)&p_ms_lo, g_ms_lo);
    cudaGetSymbolAddress((void**)&p_fu_hi, g_fu_hi);
    cudaGetSymbolAddress((void**)&p_fu_lo, g_fu_lo);
    cudaGetSymbolAddress((void**)&p_wv_hi, g_wv_hi);
    cudaGetSymbolAddress((void**)&p_wv_lo, g_wv_lo);
    cudaGetSymbolAddress((void**)&p_wo_hi, g_wo_hi);
    cudaGetSymbolAddress((void**)&p_wo_lo, g_wo_lo);

    cudaStream_t s_side;
    cudaEvent_t ev_fork, ev_w, ev_join;
    cudaStreamCreateWithFlags(&s_side, cudaStreamNonBlocking);
    cudaEventCreateWithFlags(&ev_fork, cudaEventDisableTiming);
    cudaEventCreateWithFlags(&ev_w,    cudaEventDisableTiming);
    cudaEventCreateWithFlags(&ev_join, cudaEventDisableTiming);

    // side stream: weight splits, then q-proj
    cudaEventRecord(ev_fork, 0);
    cudaStreamWaitEvent(s_side, ev_fork, 0);
    wconv_kernel<<<256, 256, 0, s_side>>>(Wv, p_wv_hi, p_wv_lo);
    wconv_kernel<<<256, 256, 0, s_side>>>(Wo, p_wo_hi, p_wo_lo);
    cudaEventRecord(ev_w, s_side);
    sgemm64<<<dim3(4, (BQ + 63) / 64), 256, 0, s_side>>>(query, Wq, bq, nullptr, p_q, BQ);
    cudaEventRecord(ev_join, s_side);

    // main chain
    prep_kernel<<<1, 256>>>(mask, ext);
    sample_kernel<<<BNQ, 256>>>(refp, intr, f0, f1, f2, f3);

    // v = ms @ Wv^T + bv  (tensor cores, 340 blocks)
    cudaStreamWaitEvent(0, ev_w, 0);
    mma_gemm<<<dim3(4, (BNQ + 127) / 128), 256>>>(p_ms_hi, p_ms_lo, p_wv_hi, p_wv_lo,
                                                  bv, nullptr, p_v, BNQ);

    // join q, then fuse
    cudaStreamWaitEvent(0, ev_join, 0);
    maxfuse_kernel<<<(BQ * (C_ / 4) + 255) / 256, 256>>>();

    // out = (fused @ Wo^T + bo) * keep  (tensor cores, 60 blocks)
    mma_gemm<<<dim3(4, (BQ + 127) / 128), 256>>>(p_fu_hi, p_fu_lo, p_wo_hi, p_wo_lo,
                                                 bo, p_keep, out, BQ);
}